// round 10
// baseline (speedup 1.0000x reference)
#include <cuda_runtime.h>
#include <cstdint>

// ---------------- problem constants ----------------
#define WW 512
#define HH 512
#define HWSZ (512*512)          // 262144
#define BN 8
#define NPLANE (BN*HWSZ)        // 2,097,152
#define NCH 24                  // B*3

// ---------------- scratch ----------------
__device__ float g_a[NPLANE];
__device__ float g_b[NPLANE];
__device__ float g_gray[NPLANE];
__device__ float g_h0[NPLANE];
__device__ float g_h1[NPLANE];
__device__ float g_h2[NPLANE];      // t_final
__device__ float g_h3[NPLANE];
__device__ unsigned short g_J16[3*NPLANE];

__device__ unsigned g_hist1[NCH][256];
__device__ unsigned g_hist2[NCH][2][256];
__device__ unsigned g_bin1[NCH][2];
__device__ unsigned g_rank1[NCH][2];
__device__ float    g_pvals[NCH][2];

__device__ __forceinline__ int refl(int i, int n) {
    i = (i < 0) ? -i : i;
    return (i >= n) ? (2*n - 2 - i) : i;
}
__device__ __forceinline__ int clampr(int r) {
    if (r < 1) r = 1;
    if (r > 50) r = 50;
    return r;
}

// ============ K1: fused t0/gray/tg + horizontal box of 4 streams ============
// 256 threads, 2 outputs/thread.
__global__ __launch_bounds__(256) void k_front(const float* __restrict__ img,
                                               const float* __restrict__ omega,
                                               const float* __restrict__ atm,
                                               const int* __restrict__ rp) {
    int r = clampr(rp[0]);
    int row = blockIdx.x;
    int b = row >> 9, y = row & 511;

    // zero hist1 (24*256 = 6144 entries over 4096 blocks)
    if (threadIdx.x < 2) {
        int j = row * 2 + threadIdx.x;
        if (j < NCH*256) (&g_hist1[0][0])[j] = 0;
    }

    __shared__ float t0p[512], t0c[512];
    __shared__ float sg[612], st[612], sgt[612], sgg[612];

    float om = omega[b];
    float a0 = atm[b*3+0] + 1e-8f;
    float a1 = atm[b*3+1] + 1e-8f;
    float a2 = atm[b*3+2] + 1e-8f;
    const float* ib = img + (size_t)b * 3 * HWSZ;
    int yp = (y == 0) ? 0 : y - 1;
    int rowbase = b * HWSZ + y * WW;

    for (int x = threadIdx.x; x < 512; x += 256) {
        float rv = ib[yp*WW + x], gv = ib[HWSZ + yp*WW + x], bv = ib[2*HWSZ + yp*WW + x];
        float dark = fminf(rv/a0, fminf(gv/a1, bv/a2));
        t0p[x] = 1.0f - om * dark;
        float rc = ib[y*WW + x], gc = ib[HWSZ + y*WW + x], bc = ib[2*HWSZ + y*WW + x];
        float darkc = fminf(rc/a0, fminf(gc/a1, bc/a2));
        t0c[x] = 1.0f - om * darkc;
        float gy = 0.299f*rc + 0.587f*gc + 0.114f*bc;
        sg[r + x] = gy;
        g_gray[rowbase + x] = gy;
    }
    __syncthreads();

    for (int x = threadIdx.x; x < 512; x += 256) {
        float txv = (x == 0) ? t0p[0]
                             : t0p[x-1] * expf(-fabsf(t0p[x] - t0p[x-1]));
        float tgv = (y == 0) ? txv
                             : txv * expf(-fabsf(t0c[x] - t0p[x]));
        st[r + x] = tgv;
    }
    __syncthreads();

    for (int i = threadIdx.x; i < r; i += 256) {
        sg[i] = sg[r + (r - i)];
        st[i] = st[r + (r - i)];
        sg[r + 512 + i] = sg[r + 510 - i];
        st[r + 512 + i] = st[r + 510 - i];
    }
    __syncthreads();

    int pw = 512 + 2*r;
    for (int i = threadIdx.x; i < pw; i += 256) {
        float g = sg[i], t = st[i];
        sgt[i] = g * t;
        sgg[i] = g * g;
    }
    __syncthreads();

    int x0 = threadIdx.x * 2;
    int k = 2*r + 1;
    float s0 = 0.f, s1 = 0.f, s2 = 0.f, s3 = 0.f;
    for (int d = 0; d < k; d++) {
        s0 += sg[x0+d]; s1 += st[x0+d]; s2 += sgt[x0+d]; s3 += sgg[x0+d];
    }
    float2 o0, o1, o2, o3;
    o0.x = s0; o1.x = s1; o2.x = s2; o3.x = s3;
    {
        int add = x0 + k, sub = x0;
        o0.y = s0 + sg[add]  - sg[sub];
        o1.y = s1 + st[add]  - st[sub];
        o2.y = s2 + sgt[add] - sgt[sub];
        o3.y = s3 + sgg[add] - sgg[sub];
    }
    int base = rowbase + x0;
    *(float2*)(g_h0 + base) = o0;
    *(float2*)(g_h1 + base) = o1;
    *(float2*)(g_h2 + base) = o2;
    *(float2*)(g_h3 + base) = o3;
}

// ============ K2: vertical box (sliding, SEG=8) + a,b ============
#define SEG 8
#define NSEG (HH/SEG)           // 64
__global__ __launch_bounds__(256, 4) void k_vbox4(const int* __restrict__ rp) {
    int r = clampr(rp[0]);
    int k = 2*r + 1;
    float inv = 1.0f / ((float)k * (float)k);
    int t = blockIdx.x * blockDim.x + threadIdx.x;
    int x = t & 511;
    int q = t >> 9;
    int b = q & 7;
    int seg = q >> 3;
    int y0 = seg * SEG;
    const float* p0 = g_h0 + b*HWSZ + x;
    const float* p1 = g_h1 + b*HWSZ + x;
    const float* p2 = g_h2 + b*HWSZ + x;
    const float* p3 = g_h3 + b*HWSZ + x;
    // init window: two independent partial accumulators per stream -> higher MLP
    float s0a = 0.f, s1a = 0.f, s2a = 0.f, s3a = 0.f;
    float s0b = 0.f, s1b = 0.f, s2b = 0.f, s3b = 0.f;
    bool interior = (y0 - r >= 0) && (y0 + SEG + r < HH);
    if (interior) {
        int d = -r;
        #pragma unroll 2
        for (; d + 1 <= r; d += 2) {
            int offa = (y0 + d) * WW;
            int offb = (y0 + d + 1) * WW;
            s0a += p0[offa]; s1a += p1[offa]; s2a += p2[offa]; s3a += p3[offa];
            s0b += p0[offb]; s1b += p1[offb]; s2b += p2[offb]; s3b += p3[offb];
        }
        if (d <= r) {
            int off = (y0 + d) * WW;
            s0a += p0[off]; s1a += p1[off]; s2a += p2[off]; s3a += p3[off];
        }
    } else {
        for (int d = -r; d <= r; d++) {
            int off = refl(y0 + d, HH) * WW;
            s0a += p0[off]; s1a += p1[off]; s2a += p2[off]; s3a += p3[off];
        }
    }
    float s0 = s0a + s0b, s1 = s1a + s1b, s2 = s2a + s2b, s3 = s3a + s3b;
    float* pa = g_a + b*HWSZ + x;
    float* pb = g_b + b*HWSZ + x;
    if (interior) {
        #pragma unroll
        for (int y = y0; y < y0 + SEG; y++) {
            float mI  = s0*inv, mp  = s1*inv;
            float mIp = s2*inv, mII = s3*inv;
            float a = (mIp - mI*mp) / ((mII - mI*mI) + 0.5f);
            pa[y*WW] = a;
            pb[y*WW] = mp - a*mI;
            int ya = (y + 1 + r) * WW;
            int ys = (y - r) * WW;
            s0 += p0[ya] - p0[ys];
            s1 += p1[ya] - p1[ys];
            s2 += p2[ya] - p2[ys];
            s3 += p3[ya] - p3[ys];
        }
    } else {
        for (int y = y0; y < y0 + SEG; y++) {
            float mI  = s0*inv, mp  = s1*inv;
            float mIp = s2*inv, mII = s3*inv;
            float a = (mIp - mI*mp) / ((mII - mI*mI) + 0.5f);
            pa[y*WW] = a;
            pb[y*WW] = mp - a*mI;
            int ya = refl(y + 1 + r, HH) * WW;
            int ys = refl(y - r, HH) * WW;
            s0 += p0[ya] - p0[ys];
            s1 += p1[ya] - p1[ys];
            s2 += p2[ya] - p2[ys];
            s3 += p3[ya] - p3[ys];
        }
    }
}

// ============ K3: horizontal box of {a,b} ============
__global__ __launch_bounds__(128) void k_hbox2(const int* __restrict__ rp) {
    int r = clampr(rp[0]);
    int row = blockIdx.x;
    int b = row >> 9, y = row & 511;
    __shared__ float sa[612], sb[612];
    int rowbase = b * HWSZ + y * WW;
    for (int x = threadIdx.x; x < 512; x += 128) {
        sa[r + x] = g_a[rowbase + x];
        sb[r + x] = g_b[rowbase + x];
    }
    __syncthreads();
    for (int i = threadIdx.x; i < r; i += 128) {
        sa[i] = sa[r + (r - i)];
        sb[i] = sb[r + (r - i)];
        sa[r + 512 + i] = sa[r + 510 - i];
        sb[r + 512 + i] = sb[r + 510 - i];
    }
    __syncthreads();
    int x0 = threadIdx.x * 4;
    int k = 2*r + 1;
    float s0 = 0.f, s1 = 0.f;
    for (int d = 0; d < k; d++) { s0 += sa[x0+d]; s1 += sb[x0+d]; }
    float4 o0, o1;
    o0.x = s0; o1.x = s1;
    #pragma unroll
    for (int j = 1; j < 4; j++) {
        int add = x0 + k - 1 + j, sub = x0 + j - 1;
        s0 += sa[add] - sa[sub];
        s1 += sb[add] - sb[sub];
        ((float*)&o0)[j] = s0; ((float*)&o1)[j] = s1;
    }
    *(float4*)(g_h0 + rowbase + x0) = o0;
    *(float4*)(g_h1 + rowbase + x0) = o1;
}

// ============ K4: vertical box of {a,b} (SEG=8) + t_final ============
__global__ __launch_bounds__(256, 4) void k_vbox2(const int* __restrict__ rp) {
    int r = clampr(rp[0]);
    int k = 2*r + 1;
    float inv = 1.0f / ((float)k * (float)k);
    int t = blockIdx.x * blockDim.x + threadIdx.x;
    int x = t & 511;
    int q = t >> 9;
    int b = q & 7;
    int seg = q >> 3;
    int y0 = seg * SEG;
    const float* p0 = g_h0 + b*HWSZ + x;
    const float* p1 = g_h1 + b*HWSZ + x;
    const float* pg = g_gray + b*HWSZ + x;
    float s0a = 0.f, s1a = 0.f, s0b = 0.f, s1b = 0.f;
    bool interior = (y0 - r >= 0) && (y0 + SEG + r < HH);
    if (interior) {
        int d = -r;
        #pragma unroll 4
        for (; d + 1 <= r; d += 2) {
            int offa = (y0 + d) * WW;
            int offb = (y0 + d + 1) * WW;
            s0a += p0[offa]; s1a += p1[offa];
            s0b += p0[offb]; s1b += p1[offb];
        }
        if (d <= r) {
            int off = (y0 + d) * WW;
            s0a += p0[off]; s1a += p1[off];
        }
    } else {
        for (int d = -r; d <= r; d++) {
            int off = refl(y0 + d, HH) * WW;
            s0a += p0[off]; s1a += p1[off];
        }
    }
    float s0 = s0a + s0b, s1 = s1a + s1b;
    float* pt = g_h2 + b*HWSZ + x;   // t_final
    if (interior) {
        #pragma unroll
        for (int y = y0; y < y0 + SEG; y++) {
            float tf = (s0*inv) * pg[y*WW] + (s1*inv);
            pt[y*WW] = fminf(fmaxf(tf, 0.1f), 1.0f);
            int ya = (y + 1 + r) * WW;
            int ys = (y - r) * WW;
            s0 += p0[ya] - p0[ys];
            s1 += p1[ya] - p1[ys];
        }
    } else {
        for (int y = y0; y < y0 + SEG; y++) {
            float tf = (s0*inv) * pg[y*WW] + (s1*inv);
            pt[y*WW] = fminf(fmaxf(tf, 0.1f), 1.0f);
            int ya = refl(y + 1 + r, HH) * WW;
            int ys = refl(y - r, HH) * WW;
            s0 += p0[ya] - p0[ys];
            s1 += p1[ya] - p1[ys];
        }
    }
}

// ============ K5: restoration J -> u16 + stage-1 8-bit histogram ============
__global__ __launch_bounds__(256) void k_Jq(const float* __restrict__ img,
                                            const float* __restrict__ atm) {
    __shared__ unsigned sh[256];
    int tid = threadIdx.x;
    sh[tid] = 0;
    __syncthreads();
    int bc = blockIdx.y;
    int b = bc / 3;
    float A = atm[bc];
    size_t base = (size_t)bc * HWSZ + (size_t)blockIdx.x * 8192;
    const float4* ip = (const float4*)(img + base);
    const float4* tp = (const float4*)(g_h2 + (size_t)b * HWSZ + (size_t)blockIdx.x * 8192);
    ushort4* Jp = (ushort4*)(g_J16 + base);
    #pragma unroll
    for (int i = 0; i < 8; i++) {
        int o = i*256 + tid;
        float4 iv = ip[o];
        float4 tf = tp[o];
        float v0 = fminf(fmaxf((iv.x - A) / (tf.x + 1e-8f) + A, 0.0f), 1.0f);
        float v1 = fminf(fmaxf((iv.y - A) / (tf.y + 1e-8f) + A, 0.0f), 1.0f);
        float v2 = fminf(fmaxf((iv.z - A) / (tf.z + 1e-8f) + A, 0.0f), 1.0f);
        float v3 = fminf(fmaxf((iv.w - A) / (tf.w + 1e-8f) + A, 0.0f), 1.0f);
        ushort4 qv;
        qv.x = (unsigned short)(v0 * 65535.0f + 0.5f);
        qv.y = (unsigned short)(v1 * 65535.0f + 0.5f);
        qv.z = (unsigned short)(v2 * 65535.0f + 0.5f);
        qv.w = (unsigned short)(v3 * 65535.0f + 0.5f);
        Jp[o] = qv;
        atomicAdd(&sh[qv.x >> 8], 1u);
        atomicAdd(&sh[qv.y >> 8], 1u);
        atomicAdd(&sh[qv.z >> 8], 1u);
        atomicAdd(&sh[qv.w >> 8], 1u);
    }
    __syncthreads();
    if (sh[tid]) atomicAdd(&g_hist1[bc][tid], sh[tid]);
}

// ============ K6: stage-1 select (+ zero hist2) ============
__global__ void k_sel1(const float* __restrict__ Llow,
                       const float* __restrict__ Lhigh) {
    int bc = blockIdx.x;
    int b = bc / 3;
    {
        unsigned* h2 = &g_hist2[bc][0][0];
        for (int i = threadIdx.x; i < 512; i += 64) h2[i] = 0;
    }
    if (threadIdx.x == 0) {
        const unsigned* h = g_hist1[bc];
        for (int slot = 0; slot < 2; slot++) {
            float Lv = (slot == 0) ? Llow[b] : Lhigh[b];
            int tgt = (int)((Lv / 100.0f) * (float)HWSZ);
            if (tgt < 0) tgt = 0;
            if (tgt > HWSZ - 1) tgt = HWSZ - 1;
            unsigned cum = 0;
            int bin = 0;
            for (; bin < 256; bin++) {
                if (cum + h[bin] > (unsigned)tgt) break;
                cum += h[bin];
            }
            g_bin1[bc][slot]  = (unsigned)bin;
            g_rank1[bc][slot] = (unsigned)tgt - cum;
        }
    }
}

// ============ K7: stage-2 8-bit histogram on u16 keys ============
__global__ __launch_bounds__(256) void k_hist2q() {
    __shared__ unsigned shL[256], shH[256];
    int tid = threadIdx.x;
    shL[tid] = 0; shH[tid] = 0;
    __syncthreads();
    int bc = blockIdx.y;
    unsigned binL = g_bin1[bc][0];
    unsigned binH = g_bin1[bc][1];
    const uint4* Jp = (const uint4*)(g_J16 + (size_t)bc * HWSZ + (size_t)blockIdx.x * 8192);
    #pragma unroll
    for (int i = 0; i < 4; i++) {
        uint4 v = Jp[i*256 + tid];
        #pragma unroll
        for (int j = 0; j < 4; j++) {
            unsigned w = ((const unsigned*)&v)[j];
            unsigned q0 = w & 0xFFFFu, q1 = w >> 16;
            if ((q0 >> 8) == binL) atomicAdd(&shL[q0 & 0xFFu], 1u);
            if ((q0 >> 8) == binH) atomicAdd(&shH[q0 & 0xFFu], 1u);
            if ((q1 >> 8) == binL) atomicAdd(&shL[q1 & 0xFFu], 1u);
            if ((q1 >> 8) == binH) atomicAdd(&shH[q1 & 0xFFu], 1u);
        }
    }
    __syncthreads();
    if (shL[tid]) atomicAdd(&g_hist2[bc][0][tid], shL[tid]);
    if (shH[tid]) atomicAdd(&g_hist2[bc][1][tid], shH[tid]);
}

// ============ K8: final select -> p_low / p_high ============
__global__ void k_sel2() {
    int bc = blockIdx.x;
    if (threadIdx.x == 0) {
        for (int slot = 0; slot < 2; slot++) {
            unsigned tgt = g_rank1[bc][slot];
            const unsigned* h = g_hist2[bc][slot];
            unsigned cum = 0;
            int bin = 0;
            for (; bin < 256; bin++) {
                if (cum + h[bin] > tgt) break;
                cum += h[bin];
            }
            unsigned key = (g_bin1[bc][slot] << 8) | (unsigned)bin;
            g_pvals[bc][slot] = (float)key * (1.0f / 65535.0f);
        }
    }
}

// ============ K9: final normalize (u16 -> float out) ============
__global__ __launch_bounds__(256) void k_out(float* __restrict__ out) {
    int idx4 = blockIdx.x * 256 + threadIdx.x;   // one uint2 = 4 pixels
    if (idx4 >= (3*NPLANE)/4) return;
    int bc = idx4 >> 16;                          // 65536 groups per plane
    float pl = g_pvals[bc][0];
    float ph = g_pvals[bc][1];
    float denom = 1.0f / (ph - pl + 1e-8f);
    uint2 v = ((const uint2*)g_J16)[idx4];
    const float s = 1.0f / 65535.0f;
    float j0 = (float)(v.x & 0xFFFFu) * s;
    float j1 = (float)(v.x >> 16) * s;
    float j2 = (float)(v.y & 0xFFFFu) * s;
    float j3 = (float)(v.y >> 16) * s;
    float4 o;
    o.x = fminf(fmaxf((fminf(fmaxf(j0, pl), ph) - pl) * denom, 0.0f), 1.0f);
    o.y = fminf(fmaxf((fminf(fmaxf(j1, pl), ph) - pl) * denom, 0.0f), 1.0f);
    o.z = fminf(fmaxf((fminf(fmaxf(j2, pl), ph) - pl) * denom, 0.0f), 1.0f);
    o.w = fminf(fmaxf((fminf(fmaxf(j3, pl), ph) - pl) * denom, 0.0f), 1.0f);
    ((float4*)out)[idx4] = o;
}

// ---------------- launch ----------------
extern "C" void kernel_launch(void* const* d_in, const int* in_sizes, int n_in,
                              void* d_out, int out_size) {
    const float* img   = (const float*)d_in[0];
    const float* omega = (const float*)d_in[1];
    const float* atm   = (const float*)d_in[2];
    const float* Llow  = (const float*)d_in[3];
    const float* Lhigh = (const float*)d_in[4];
    const int*   rp    = (const int*)d_in[5];
    float* out = (float*)d_out;

    (void)in_sizes; (void)n_in; (void)out_size;

    k_front<<<BN*HH, 256>>>(img, omega, atm, rp);
    k_vbox4<<<(BN*WW*NSEG)/256, 256>>>(rp);
    k_hbox2<<<BN*HH, 128>>>(rp);
    k_vbox2<<<(BN*WW*NSEG)/256, 256>>>(rp);
    dim3 gJ(HWSZ/8192, NCH);
    k_Jq<<<gJ, 256>>>(img, atm);
    k_sel1<<<NCH, 64>>>(Llow, Lhigh);
    k_hist2q<<<gJ, 256>>>();
    k_sel2<<<NCH, 32>>>();
    k_out<<<((3*NPLANE)/4 + 255)/256, 256>>>(out);
}

// round 11
// speedup vs baseline: 1.8764x; 1.8764x over previous
#include <cuda_runtime.h>
#include <cstdint>

// ---------------- problem constants ----------------
#define WW 512
#define HH 512
#define HWSZ (512*512)          // 262144
#define BN 8
#define NPLANE (BN*HWSZ)        // 2,097,152
#define NCH 24                  // B*3

// ---------------- scratch ----------------
__device__ float g_a[NPLANE];
__device__ float g_b[NPLANE];
__device__ float g_gray[NPLANE];
__device__ float g_h0[NPLANE];
__device__ float g_h1[NPLANE];
__device__ float g_h2[NPLANE];      // t_final
__device__ float g_h3[NPLANE];
__device__ unsigned short g_J16[3*NPLANE];   // 12-bit keys in u16

__device__ unsigned g_hist1[NCH][4096];
__device__ float    g_pvals[NCH][2];

__device__ __forceinline__ int refl(int i, int n) {
    i = (i < 0) ? -i : i;
    return (i >= n) ? (2*n - 2 - i) : i;
}
__device__ __forceinline__ int clampr(int r) {
    if (r < 1) r = 1;
    if (r > 50) r = 50;
    return r;
}

// ============ K1: fused t0/gray/tg + horizontal box of 4 streams ============
__global__ __launch_bounds__(128) void k_front(const float* __restrict__ img,
                                               const float* __restrict__ omega,
                                               const float* __restrict__ atm,
                                               const int* __restrict__ rp) {
    int r = clampr(rp[0]);
    int row = blockIdx.x;
    int b = row >> 9, y = row & 511;

    // zero hist1 (24*4096 = 98304 entries over 4096 blocks = 24 each)
    {
        unsigned* h1 = &g_hist1[0][0];
        int base = row * 24;
        for (int i = threadIdx.x; i < 24; i += 128) h1[base + i] = 0;
    }

    __shared__ float t0p[512], t0c[512];
    __shared__ float sg[612], st[612], sgt[612], sgg[612];

    float om = omega[b];
    float a0 = atm[b*3+0] + 1e-8f;
    float a1 = atm[b*3+1] + 1e-8f;
    float a2 = atm[b*3+2] + 1e-8f;
    const float* ib = img + (size_t)b * 3 * HWSZ;
    int yp = (y == 0) ? 0 : y - 1;
    int rowbase = b * HWSZ + y * WW;

    for (int x = threadIdx.x; x < 512; x += 128) {
        float rv = ib[yp*WW + x], gv = ib[HWSZ + yp*WW + x], bv = ib[2*HWSZ + yp*WW + x];
        float dark = fminf(rv/a0, fminf(gv/a1, bv/a2));
        t0p[x] = 1.0f - om * dark;
        float rc = ib[y*WW + x], gc = ib[HWSZ + y*WW + x], bc = ib[2*HWSZ + y*WW + x];
        float darkc = fminf(rc/a0, fminf(gc/a1, bc/a2));
        t0c[x] = 1.0f - om * darkc;
        float gy = 0.299f*rc + 0.587f*gc + 0.114f*bc;
        sg[r + x] = gy;
        g_gray[rowbase + x] = gy;
    }
    __syncthreads();

    for (int x = threadIdx.x; x < 512; x += 128) {
        float txv = (x == 0) ? t0p[0]
                             : t0p[x-1] * expf(-fabsf(t0p[x] - t0p[x-1]));
        float tgv = (y == 0) ? txv
                             : txv * expf(-fabsf(t0c[x] - t0p[x]));
        st[r + x] = tgv;
    }
    __syncthreads();

    for (int i = threadIdx.x; i < r; i += 128) {
        sg[i] = sg[r + (r - i)];
        st[i] = st[r + (r - i)];
        sg[r + 512 + i] = sg[r + 510 - i];
        st[r + 512 + i] = st[r + 510 - i];
    }
    __syncthreads();

    int pw = 512 + 2*r;
    for (int i = threadIdx.x; i < pw; i += 128) {
        float g = sg[i], t = st[i];
        sgt[i] = g * t;
        sgg[i] = g * g;
    }
    __syncthreads();

    int x0 = threadIdx.x * 4;
    int k = 2*r + 1;
    float s0 = 0.f, s1 = 0.f, s2 = 0.f, s3 = 0.f;
    for (int d = 0; d < k; d++) {
        s0 += sg[x0+d]; s1 += st[x0+d]; s2 += sgt[x0+d]; s3 += sgg[x0+d];
    }
    float4 o0, o1, o2, o3;
    o0.x = s0; o1.x = s1; o2.x = s2; o3.x = s3;
    #pragma unroll
    for (int j = 1; j < 4; j++) {
        int add = x0 + k - 1 + j, sub = x0 + j - 1;
        s0 += sg[add] - sg[sub];
        s1 += st[add] - st[sub];
        s2 += sgt[add] - sgt[sub];
        s3 += sgg[add] - sgg[sub];
        ((float*)&o0)[j] = s0; ((float*)&o1)[j] = s1;
        ((float*)&o2)[j] = s2; ((float*)&o3)[j] = s3;
    }
    int base = rowbase + x0;
    *(float4*)(g_h0 + base) = o0;
    *(float4*)(g_h1 + base) = o1;
    *(float4*)(g_h2 + base) = o2;
    *(float4*)(g_h3 + base) = o3;
}

// ============ K2: vertical box (sliding, SEG=8) + a,b ============
#define SEG 8
#define NSEG (HH/SEG)           // 64
__global__ __launch_bounds__(256) void k_vbox4(const int* __restrict__ rp) {
    int r = clampr(rp[0]);
    int k = 2*r + 1;
    float inv = 1.0f / ((float)k * (float)k);
    int t = blockIdx.x * blockDim.x + threadIdx.x;
    int x = t & 511;
    int q = t >> 9;
    int b = q & 7;
    int seg = q >> 3;
    int y0 = seg * SEG;
    const float* p0 = g_h0 + b*HWSZ + x;
    const float* p1 = g_h1 + b*HWSZ + x;
    const float* p2 = g_h2 + b*HWSZ + x;
    const float* p3 = g_h3 + b*HWSZ + x;
    float s0 = 0.f, s1 = 0.f, s2 = 0.f, s3 = 0.f;
    bool interior = (y0 - r >= 0) && (y0 + SEG + r < HH);
    if (interior) {
        for (int d = -r; d <= r; d++) {
            int off = (y0 + d) * WW;
            s0 += p0[off]; s1 += p1[off]; s2 += p2[off]; s3 += p3[off];
        }
    } else {
        for (int d = -r; d <= r; d++) {
            int off = refl(y0 + d, HH) * WW;
            s0 += p0[off]; s1 += p1[off]; s2 += p2[off]; s3 += p3[off];
        }
    }
    float* pa = g_a + b*HWSZ + x;
    float* pb = g_b + b*HWSZ + x;
    if (interior) {
        #pragma unroll
        for (int y = y0; y < y0 + SEG; y++) {
            float mI  = s0*inv, mp  = s1*inv;
            float mIp = s2*inv, mII = s3*inv;
            float a = (mIp - mI*mp) / ((mII - mI*mI) + 0.5f);
            pa[y*WW] = a;
            pb[y*WW] = mp - a*mI;
            int ya = (y + 1 + r) * WW;
            int ys = (y - r) * WW;
            s0 += p0[ya] - p0[ys];
            s1 += p1[ya] - p1[ys];
            s2 += p2[ya] - p2[ys];
            s3 += p3[ya] - p3[ys];
        }
    } else {
        for (int y = y0; y < y0 + SEG; y++) {
            float mI  = s0*inv, mp  = s1*inv;
            float mIp = s2*inv, mII = s3*inv;
            float a = (mIp - mI*mp) / ((mII - mI*mI) + 0.5f);
            pa[y*WW] = a;
            pb[y*WW] = mp - a*mI;
            int ya = refl(y + 1 + r, HH) * WW;
            int ys = refl(y - r, HH) * WW;
            s0 += p0[ya] - p0[ys];
            s1 += p1[ya] - p1[ys];
            s2 += p2[ya] - p2[ys];
            s3 += p3[ya] - p3[ys];
        }
    }
}

// ============ K3: horizontal box of {a,b} ============
__global__ __launch_bounds__(128) void k_hbox2(const int* __restrict__ rp) {
    int r = clampr(rp[0]);
    int row = blockIdx.x;
    int b = row >> 9, y = row & 511;
    __shared__ float sa[612], sb[612];
    int rowbase = b * HWSZ + y * WW;
    for (int x = threadIdx.x; x < 512; x += 128) {
        sa[r + x] = g_a[rowbase + x];
        sb[r + x] = g_b[rowbase + x];
    }
    __syncthreads();
    for (int i = threadIdx.x; i < r; i += 128) {
        sa[i] = sa[r + (r - i)];
        sb[i] = sb[r + (r - i)];
        sa[r + 512 + i] = sa[r + 510 - i];
        sb[r + 512 + i] = sb[r + 510 - i];
    }
    __syncthreads();
    int x0 = threadIdx.x * 4;
    int k = 2*r + 1;
    float s0 = 0.f, s1 = 0.f;
    for (int d = 0; d < k; d++) { s0 += sa[x0+d]; s1 += sb[x0+d]; }
    float4 o0, o1;
    o0.x = s0; o1.x = s1;
    #pragma unroll
    for (int j = 1; j < 4; j++) {
        int add = x0 + k - 1 + j, sub = x0 + j - 1;
        s0 += sa[add] - sa[sub];
        s1 += sb[add] - sb[sub];
        ((float*)&o0)[j] = s0; ((float*)&o1)[j] = s1;
    }
    *(float4*)(g_h0 + rowbase + x0) = o0;
    *(float4*)(g_h1 + rowbase + x0) = o1;
}

// ============ K4: vertical box of {a,b} (SEG=8) + t_final ============
__global__ __launch_bounds__(256) void k_vbox2(const int* __restrict__ rp) {
    int r = clampr(rp[0]);
    int k = 2*r + 1;
    float inv = 1.0f / ((float)k * (float)k);
    int t = blockIdx.x * blockDim.x + threadIdx.x;
    int x = t & 511;
    int q = t >> 9;
    int b = q & 7;
    int seg = q >> 3;
    int y0 = seg * SEG;
    const float* p0 = g_h0 + b*HWSZ + x;
    const float* p1 = g_h1 + b*HWSZ + x;
    const float* pg = g_gray + b*HWSZ + x;
    float s0 = 0.f, s1 = 0.f;
    bool interior = (y0 - r >= 0) && (y0 + SEG + r < HH);
    if (interior) {
        for (int d = -r; d <= r; d++) {
            int off = (y0 + d) * WW;
            s0 += p0[off]; s1 += p1[off];
        }
    } else {
        for (int d = -r; d <= r; d++) {
            int off = refl(y0 + d, HH) * WW;
            s0 += p0[off]; s1 += p1[off];
        }
    }
    float* pt = g_h2 + b*HWSZ + x;   // t_final
    if (interior) {
        #pragma unroll
        for (int y = y0; y < y0 + SEG; y++) {
            float tf = (s0*inv) * pg[y*WW] + (s1*inv);
            pt[y*WW] = fminf(fmaxf(tf, 0.1f), 1.0f);
            int ya = (y + 1 + r) * WW;
            int ys = (y - r) * WW;
            s0 += p0[ya] - p0[ys];
            s1 += p1[ya] - p1[ys];
        }
    } else {
        for (int y = y0; y < y0 + SEG; y++) {
            float tf = (s0*inv) * pg[y*WW] + (s1*inv);
            pt[y*WW] = fminf(fmaxf(tf, 0.1f), 1.0f);
            int ya = refl(y + 1 + r, HH) * WW;
            int ys = refl(y - r, HH) * WW;
            s0 += p0[ya] - p0[ys];
            s1 += p1[ya] - p1[ys];
        }
    }
}

// ============ K5: restoration J -> u12 + single 4096-bin histogram ============
// grid (32, NCH): each block handles 8192 pixels of one (b,c) plane.
__global__ __launch_bounds__(256) void k_Jq(const float* __restrict__ img,
                                            const float* __restrict__ atm) {
    __shared__ unsigned sh[4096];
    int tid = threadIdx.x;
    for (int i = tid; i < 4096; i += 256) sh[i] = 0;
    __syncthreads();
    int bc = blockIdx.y;
    int b = bc / 3;
    float A = atm[bc];
    size_t base = (size_t)bc * HWSZ + (size_t)blockIdx.x * 8192;
    const float4* ip = (const float4*)(img + base);
    const float4* tp = (const float4*)(g_h2 + (size_t)b * HWSZ + (size_t)blockIdx.x * 8192);
    ushort4* Jp = (ushort4*)(g_J16 + base);
    #pragma unroll
    for (int i = 0; i < 8; i++) {
        int o = i*256 + tid;
        float4 iv = ip[o];
        float4 tf = tp[o];
        float v0 = fminf(fmaxf((iv.x - A) / (tf.x + 1e-8f) + A, 0.0f), 1.0f);
        float v1 = fminf(fmaxf((iv.y - A) / (tf.y + 1e-8f) + A, 0.0f), 1.0f);
        float v2 = fminf(fmaxf((iv.z - A) / (tf.z + 1e-8f) + A, 0.0f), 1.0f);
        float v3 = fminf(fmaxf((iv.w - A) / (tf.w + 1e-8f) + A, 0.0f), 1.0f);
        ushort4 qv;
        qv.x = (unsigned short)(v0 * 4095.0f + 0.5f);
        qv.y = (unsigned short)(v1 * 4095.0f + 0.5f);
        qv.z = (unsigned short)(v2 * 4095.0f + 0.5f);
        qv.w = (unsigned short)(v3 * 4095.0f + 0.5f);
        Jp[o] = qv;
        atomicAdd(&sh[qv.x], 1u);
        atomicAdd(&sh[qv.y], 1u);
        atomicAdd(&sh[qv.z], 1u);
        atomicAdd(&sh[qv.w], 1u);
    }
    __syncthreads();
    for (int i = tid; i < 4096; i += 256) {
        unsigned v = sh[i];
        if (v) atomicAdd(&g_hist1[bc][i], v);
    }
}

// ============ K6: selection over 4096 bins -> p_low / p_high ============
__global__ __launch_bounds__(256) void k_sel(const float* __restrict__ Llow,
                                             const float* __restrict__ Lhigh) {
    int bc = blockIdx.x;
    int b = bc / 3;
    __shared__ unsigned part[256];
    const unsigned* h = g_hist1[bc];
    for (int slot = 0; slot < 2; slot++) {
        float Lv = (slot == 0) ? Llow[b] : Lhigh[b];
        int tgt = (int)((Lv / 100.0f) * (float)HWSZ);
        if (tgt < 0) tgt = 0;
        if (tgt > HWSZ - 1) tgt = HWSZ - 1;
        unsigned s = 0;
        #pragma unroll 4
        for (int j = 0; j < 16; j++) s += h[threadIdx.x*16 + j];
        part[threadIdx.x] = s;
        __syncthreads();
        if (threadIdx.x == 0) {
            unsigned cum = 0;
            int slice = 0;
            for (; slice < 256; slice++) {
                if (cum + part[slice] > (unsigned)tgt) break;
                cum += part[slice];
            }
            int bin = slice * 16;
            for (;; bin++) {
                if (cum + h[bin] > (unsigned)tgt) break;
                cum += h[bin];
            }
            g_pvals[bc][slot] = (float)bin * (1.0f / 4095.0f);
        }
        __syncthreads();
    }
}

// ============ K7: final normalize (u12 -> float out) ============
__global__ __launch_bounds__(256) void k_out(float* __restrict__ out) {
    int idx4 = blockIdx.x * 256 + threadIdx.x;   // one uint2 = 4 pixels
    if (idx4 >= (3*NPLANE)/4) return;
    int bc = idx4 >> 16;                          // 65536 groups per plane
    float pl = g_pvals[bc][0];
    float ph = g_pvals[bc][1];
    float denom = 1.0f / (ph - pl + 1e-8f);
    uint2 v = ((const uint2*)g_J16)[idx4];
    const float s = 1.0f / 4095.0f;
    float j0 = (float)(v.x & 0xFFFFu) * s;
    float j1 = (float)(v.x >> 16) * s;
    float j2 = (float)(v.y & 0xFFFFu) * s;
    float j3 = (float)(v.y >> 16) * s;
    float4 o;
    o.x = fminf(fmaxf((fminf(fmaxf(j0, pl), ph) - pl) * denom, 0.0f), 1.0f);
    o.y = fminf(fmaxf((fminf(fmaxf(j1, pl), ph) - pl) * denom, 0.0f), 1.0f);
    o.z = fminf(fmaxf((fminf(fmaxf(j2, pl), ph) - pl) * denom, 0.0f), 1.0f);
    o.w = fminf(fmaxf((fminf(fmaxf(j3, pl), ph) - pl) * denom, 0.0f), 1.0f);
    ((float4*)out)[idx4] = o;
}

// ---------------- launch ----------------
extern "C" void kernel_launch(void* const* d_in, const int* in_sizes, int n_in,
                              void* d_out, int out_size) {
    const float* img   = (const float*)d_in[0];
    const float* omega = (const float*)d_in[1];
    const float* atm   = (const float*)d_in[2];
    const float* Llow  = (const float*)d_in[3];
    const float* Lhigh = (const float*)d_in[4];
    const int*   rp    = (const int*)d_in[5];
    float* out = (float*)d_out;

    (void)in_sizes; (void)n_in; (void)out_size;

    k_front<<<BN*HH, 128>>>(img, omega, atm, rp);
    k_vbox4<<<(BN*WW*NSEG)/256, 256>>>(rp);
    k_hbox2<<<BN*HH, 128>>>(rp);
    k_vbox2<<<(BN*WW*NSEG)/256, 256>>>(rp);
    dim3 gJ(HWSZ/8192, NCH);
    k_Jq<<<gJ, 256>>>(img, atm);
    k_sel<<<NCH, 256>>>(Llow, Lhigh);
    k_out<<<((3*NPLANE)/4 + 255)/256, 256>>>(out);
}